// round 1
// baseline (speedup 1.0000x reference)
#include <cuda_runtime.h>
#include <cstdint>

// BinLinear: out = input @ sign(tanh(weight))
// sign(tanh(w)) = +1 iff w >= 0 (tanh monotone, tanh(0)=0).
// Exact decomposition, valid for ANY weight:
//   out[n,o] = rowsum(input)[n] - 2 * sum_{(i,o) : w[i,o] < 0} input[n,i]
// Phase 1: scan weight, record all negative (i,o) positions in a device list.
// Phase 2: rowsum + broadcast (memory-bound, ~128MB of traffic).
// Phase 3: apply corrections for every recorded negative position (empty for
//          weight ~ U[0,1), so near-zero cost, but fully general).

#define N_ROWS 8192
#define N_IP   2048
#define N_OP   2048

// Device-global scratch (no allocations allowed in kernel_launch).
__device__ int          g_neg_count;
__device__ unsigned int g_neg_pairs[(size_t)N_IP * N_OP];  // 16 MB worst case

__global__ void zero_count_kernel() { g_neg_count = 0; }

__global__ __launch_bounds__(256)
void scan_weight_kernel(const float4* __restrict__ w4) {
    const int total4 = (N_IP * N_OP) / 4;
    for (int idx = blockIdx.x * blockDim.x + threadIdx.x; idx < total4;
         idx += gridDim.x * blockDim.x) {
        float4 v = w4[idx];
        // Fast path: all four non-negative (the overwhelmingly common case).
        if (v.x < 0.f || v.y < 0.f || v.z < 0.f || v.w < 0.f) {
            unsigned base = (unsigned)idx * 4u;
            if (v.x < 0.f) g_neg_pairs[atomicAdd(&g_neg_count, 1)] = base + 0u;
            if (v.y < 0.f) g_neg_pairs[atomicAdd(&g_neg_count, 1)] = base + 1u;
            if (v.z < 0.f) g_neg_pairs[atomicAdd(&g_neg_count, 1)] = base + 2u;
            if (v.w < 0.f) g_neg_pairs[atomicAdd(&g_neg_count, 1)] = base + 3u;
        }
    }
}

// One block per row: reduce the row (8 KB read) then broadcast the sum into
// the output row (8 KB write). Pure streaming; no reuse needed.
__global__ __launch_bounds__(256)
void rowsum_bcast_kernel(const float* __restrict__ x, float* __restrict__ out) {
    const int row = blockIdx.x;
    const float4* xr = reinterpret_cast<const float4*>(x + (size_t)row * N_IP);

    float s = 0.f;
    #pragma unroll
    for (int j = threadIdx.x; j < N_IP / 4; j += 256) {
        float4 v = __ldg(&xr[j]);
        s += (v.x + v.y) + (v.z + v.w);
    }
    // Warp reduce.
    #pragma unroll
    for (int o = 16; o > 0; o >>= 1) s += __shfl_xor_sync(0xffffffffu, s, o);

    __shared__ float warpsum[8];
    const int lane = threadIdx.x & 31;
    const int wid  = threadIdx.x >> 5;
    if (lane == 0) warpsum[wid] = s;
    __syncthreads();
    if (wid == 0) {
        float t = (lane < 8) ? warpsum[lane] : 0.f;
        #pragma unroll
        for (int o = 4; o > 0; o >>= 1) t += __shfl_xor_sync(0xffffffffu, t, o);
        if (lane == 0) warpsum[0] = t;
    }
    __syncthreads();
    const float total = warpsum[0];

    float4 o4 = make_float4(total, total, total, total);
    float4* orow = reinterpret_cast<float4*>(out + (size_t)row * N_OP);
    #pragma unroll
    for (int j = threadIdx.x; j < N_OP / 4; j += 256) orow[j] = o4;
}

// Fixed-grid correction: loops over the recorded negative positions
// (device-side count, so the launch shape is static & graph-capturable).
// For the actual U[0,1) weight the list is empty and this returns instantly.
__global__ __launch_bounds__(256)
void correction_kernel(const float* __restrict__ x, float* __restrict__ out) {
    const int cnt = g_neg_count;
    const int stride = gridDim.x * blockDim.x;
    for (int p = 0; p < cnt; ++p) {
        const unsigned pos = g_neg_pairs[p];
        const int i = (int)(pos / N_OP);
        const int o = (int)(pos % N_OP);
        for (int n = blockIdx.x * blockDim.x + threadIdx.x; n < N_ROWS; n += stride) {
            atomicAdd(&out[(size_t)n * N_OP + o], -2.0f * x[(size_t)n * N_IP + i]);
        }
    }
}

extern "C" void kernel_launch(void* const* d_in, const int* in_sizes, int n_in,
                              void* d_out, int out_size) {
    const float* x = (const float*)d_in[0];   // input  [8192, 2048] f32
    const float* w = (const float*)d_in[1];   // weight [2048, 2048] f32
    float* out = (float*)d_out;               // out    [8192, 2048] f32

    zero_count_kernel<<<1, 1>>>();
    scan_weight_kernel<<<1024, 256>>>(reinterpret_cast<const float4*>(w));
    rowsum_bcast_kernel<<<N_ROWS, 256>>>(x, out);
    correction_kernel<<<64, 256>>>(x, out);
}

// round 3
// speedup vs baseline: 1.1080x; 1.1080x over previous
#include <cuda_runtime.h>
#include <cstdint>

// BinLinear: out = input @ sign(tanh(weight))
// sign(tanh(w)) = +1 iff w >= 0 (tanh monotone, tanh(0)=0).
// Exact decomposition, valid for ANY weight:
//   out[n,o] = rowsum(input)[n] - 2 * sum_{(i,o) : w[i,o] < 0} input[n,i]
//
// Launch structure (2 kernels, down from 4):
//   K1 rowsum_bcast : out[n,:] = rowsum(input[n,:])          (128 MB traffic)
//   K2 scan_correct : for every negative w[i,o], atomically
//                     patch column o with -2*input[:,i]       (16 MB read;
//                     zero patches for weight ~ U[0,1))
// Both are pure streaming; streaming cache hints keep L2 clean.

#define N_ROWS 8192
#define N_IP   2048
#define N_OP   2048

// One block per row: reduce the row (8 KB read) then broadcast the sum into
// the output row (8 KB write).
__global__ __launch_bounds__(256)
void rowsum_bcast_kernel(const float* __restrict__ x, float* __restrict__ out) {
    const int row = blockIdx.x;
    const float4* xr = reinterpret_cast<const float4*>(x + (size_t)row * N_IP);

    float s = 0.f;
    #pragma unroll
    for (int j = threadIdx.x; j < N_IP / 4; j += 256) {
        float4 v = __ldcs(&xr[j]);          // evict-first: single-touch read
        s += (v.x + v.y) + (v.z + v.w);
    }
    // Warp reduce.
    #pragma unroll
    for (int o = 16; o > 0; o >>= 1) s += __shfl_xor_sync(0xffffffffu, s, o);

    __shared__ float warpsum[8];
    const int lane = threadIdx.x & 31;
    const int wid  = threadIdx.x >> 5;
    if (lane == 0) warpsum[wid] = s;
    __syncthreads();
    if (wid == 0) {
        float t = (lane < 8) ? warpsum[lane] : 0.f;
        #pragma unroll
        for (int o = 4; o > 0; o >>= 1) t += __shfl_xor_sync(0xffffffffu, t, o);
        if (lane == 0) warpsum[0] = t;
    }
    __syncthreads();
    const float total = warpsum[0];

    const float4 o4 = make_float4(total, total, total, total);
    float4* orow = reinterpret_cast<float4*>(out + (size_t)row * N_OP);
    #pragma unroll
    for (int j = threadIdx.x; j < N_OP / 4; j += 256) {
        __stcs(&orow[j], o4);               // evict-first: single-touch write
    }
}

// Fused scan + correction. Runs after rowsum_bcast. Each thread streams its
// slice of the weight; for every negative element (i,o) it directly applies
// the exact correction to column o of the output. For weight ~ U[0,1) the
// branch never fires and this is a pure 16 MB streaming read (~2.5us).
__global__ __launch_bounds__(256)
void scan_correct_kernel(const float4* __restrict__ w4,
                         const float* __restrict__ x,
                         float* __restrict__ out) {
    const int total4 = (N_IP * N_OP) / 4;
    const int stride = gridDim.x * blockDim.x;
    for (int idx = blockIdx.x * blockDim.x + threadIdx.x; idx < total4;
         idx += stride) {
        const float4 v = __ldcs(&w4[idx]);
        if (v.x < 0.f || v.y < 0.f || v.z < 0.f || v.w < 0.f) {
            const unsigned base = (unsigned)idx * 4u;
            const float e[4] = {v.x, v.y, v.z, v.w};
            #pragma unroll
            for (int k = 0; k < 4; ++k) {
                if (e[k] < 0.f) {
                    const unsigned pos = base + (unsigned)k;
                    const int i = (int)(pos / N_OP);
                    const int o = (int)(pos % N_OP);
                    for (int n = 0; n < N_ROWS; ++n) {
                        atomicAdd(&out[(size_t)n * N_OP + o],
                                  -2.0f * x[(size_t)n * N_IP + i]);
                    }
                }
            }
        }
    }
}

extern "C" void kernel_launch(void* const* d_in, const int* in_sizes, int n_in,
                              void* d_out, int out_size) {
    const float* x = (const float*)d_in[0];   // input  [8192, 2048] f32
    const float* w = (const float*)d_in[1];   // weight [2048, 2048] f32
    float* out = (float*)d_out;               // out    [8192, 2048] f32

    rowsum_bcast_kernel<<<N_ROWS, 256>>>(x, out);
    scan_correct_kernel<<<1184, 256>>>(reinterpret_cast<const float4*>(w), x, out);
}